// round 1
// baseline (speedup 1.0000x reference)
#include <cuda_runtime.h>
#include <cstdint>

#define BATCH  2
#define SEQ    2048
#define DIM    2048
#define NH     32
#define NKV    8
#define HD     64
#define KVDIM  (NKV*HD)     // 512
#define REP    (NH/NKV)     // 4
#define HALFD  (HD/2)       // 32

// ---------------- scratch (device globals; no allocations allowed) ----------
__device__ __align__(16) float g_q[(size_t)BATCH*SEQ*NH*HD];   // 32 MB
__device__ __align__(16) float g_k[(size_t)BATCH*SEQ*NKV*HD];  // 8 MB
__device__ __align__(16) float g_v[(size_t)BATCH*SEQ*NKV*HD];  // 8 MB
__device__ __align__(16) float g_o[(size_t)BATCH*SEQ*NH*HD];   // 32 MB

// ---------------------------------------------------------------------------
// Generic GEMM: C[M,N] = A[M,K] * W[N,K]^T   (both row-major)
// 64x64 output tile, BK=16, 256 threads, 4x4 fragment per thread.
// Smem tiles stored transposed ([k][m] / [k][n]) so inner loop uses LDS.128.
// ---------------------------------------------------------------------------
__global__ void __launch_bounds__(256)
gemm_nt_kernel(const float* __restrict__ A, const float* __restrict__ W,
               float* __restrict__ C, int M, int N, int K)
{
    __shared__ float As[16][64];
    __shared__ float Ws[16][64];

    const int m0 = blockIdx.y * 64;
    const int n0 = blockIdx.x * 64;
    const int tid = threadIdx.x;
    const int ty = tid >> 4;          // 0..15
    const int tx = tid & 15;          // 0..15

    float acc[4][4] = {};

    const int r  = tid >> 2;          // 0..63 (tile row for loads)
    const int c4 = (tid & 3) << 2;    // 0,4,8,12 (k offset for loads)

    for (int k0 = 0; k0 < K; k0 += 16) {
        // load A tile (64 x 16) transposed
        float4 av = *(const float4*)(A + (size_t)(m0 + r) * K + k0 + c4);
        As[c4 + 0][r] = av.x; As[c4 + 1][r] = av.y;
        As[c4 + 2][r] = av.z; As[c4 + 3][r] = av.w;
        // load W tile (64 x 16) transposed
        float4 wv = *(const float4*)(W + (size_t)(n0 + r) * K + k0 + c4);
        Ws[c4 + 0][r] = wv.x; Ws[c4 + 1][r] = wv.y;
        Ws[c4 + 2][r] = wv.z; Ws[c4 + 3][r] = wv.w;
        __syncthreads();

        #pragma unroll
        for (int kk = 0; kk < 16; kk++) {
            float4 a = *(const float4*)&As[kk][ty << 2];
            float4 w = *(const float4*)&Ws[kk][tx << 2];
            acc[0][0] += a.x * w.x; acc[0][1] += a.x * w.y; acc[0][2] += a.x * w.z; acc[0][3] += a.x * w.w;
            acc[1][0] += a.y * w.x; acc[1][1] += a.y * w.y; acc[1][2] += a.y * w.z; acc[1][3] += a.y * w.w;
            acc[2][0] += a.z * w.x; acc[2][1] += a.z * w.y; acc[2][2] += a.z * w.z; acc[2][3] += a.z * w.w;
            acc[3][0] += a.w * w.x; acc[3][1] += a.w * w.y; acc[3][2] += a.w * w.z; acc[3][3] += a.w * w.w;
        }
        __syncthreads();
    }

    #pragma unroll
    for (int i = 0; i < 4; i++) {
        float4 o4 = make_float4(acc[i][0], acc[i][1], acc[i][2], acc[i][3]);
        *(float4*)(C + (size_t)(m0 + (ty << 2) + i) * N + n0 + (tx << 2)) = o4;
    }
}

// ---------------------------------------------------------------------------
// RoPE (interleaved pairs), in place. t layout: [B, S, nh, HD].
// ---------------------------------------------------------------------------
__global__ void rope_kernel(float* __restrict__ t,
                            const float* __restrict__ fcos,
                            const float* __restrict__ fsin,
                            int nh)
{
    int idx = blockIdx.x * blockDim.x + threadIdx.x;
    int total = BATCH * SEQ * nh * HALFD;
    if (idx >= total) return;
    int p = idx & (HALFD - 1);
    int h = (idx >> 5) % nh;
    int s = (idx >> 5) / nh % SEQ;
    int b = idx / (HALFD * nh * SEQ);

    float* base = t + (((size_t)(b * SEQ + s) * nh + h) * HD) + 2 * p;
    float cv = fcos[s * HALFD + p];
    float sv = fsin[s * HALFD + p];
    float x0 = base[0], x1 = base[1];
    base[0] = x0 * cv - x1 * sv;
    base[1] = x0 * sv + x1 * cv;
}

// ---------------------------------------------------------------------------
// Flash attention (fp32, causal, GQA). Grid: (S/64, NH, B). 256 threads.
// Tiles: 64 q-rows x 64 kv-cols. Online softmax; row stats reduced with
// width-16 shuffles (the 16 tx-threads of one ty sit in one half-warp).
// Smem: Qs (transposed) + KPs (K transposed, then reused for P) + Vs = 48 KB.
// ---------------------------------------------------------------------------
__global__ void __launch_bounds__(256)
attn_kernel(const float* __restrict__ q, const float* __restrict__ k,
            const float* __restrict__ v, float* __restrict__ o)
{
    __shared__ float Qs[HD][64];    // [d][row], pre-scaled by 1/sqrt(D)
    __shared__ float KPs[64][64];   // K as [d][col]; later P as [s][row]
    __shared__ float Vs[64][64];    // [s][d]

    const int qb  = blockIdx.x;
    const int h   = blockIdx.y;
    const int b   = blockIdx.z;
    const int kvh = h / REP;
    const int tid = threadIdx.x;
    const int ty  = tid >> 4;
    const int tx  = tid & 15;

    const float scale = 0.125f;     // 1/sqrt(64)

    // load Q tile transposed, scaled
    for (int i = tid; i < 1024; i += 256) {
        int rr = i >> 4, d4 = (i & 15) << 2;
        float4 v4 = *(const float4*)(q + (size_t)(b * SEQ + qb * 64 + rr) * DIM + h * HD + d4);
        Qs[d4 + 0][rr] = v4.x * scale; Qs[d4 + 1][rr] = v4.y * scale;
        Qs[d4 + 2][rr] = v4.z * scale; Qs[d4 + 3][rr] = v4.w * scale;
    }

    float acc[4][4] = {};
    float m_i[4] = {-1e30f, -1e30f, -1e30f, -1e30f};
    float l_i[4] = {};

    for (int t = 0; t <= qb; t++) {
        const int s0 = t * 64;
        __syncthreads();   // protect KPs/Vs from previous iteration consumers
        for (int i = tid; i < 1024; i += 256) {
            int cc = i >> 4, d4 = (i & 15) << 2;
            size_t gk = (size_t)(b * SEQ + s0 + cc) * KVDIM + kvh * HD + d4;
            float4 kv4 = *(const float4*)(k + gk);
            KPs[d4 + 0][cc] = kv4.x; KPs[d4 + 1][cc] = kv4.y;
            KPs[d4 + 2][cc] = kv4.z; KPs[d4 + 3][cc] = kv4.w;
            *(float4*)&Vs[cc][d4] = *(const float4*)(v + gk);
        }
        __syncthreads();

        // S = Q K^T  (64x64), per-thread 4x4
        float sf[4][4] = {};
        #pragma unroll 16
        for (int kk = 0; kk < HD; kk++) {
            float4 qv = *(const float4*)&Qs[kk][ty << 2];
            float4 kv = *(const float4*)&KPs[kk][tx << 2];
            sf[0][0] += qv.x * kv.x; sf[0][1] += qv.x * kv.y; sf[0][2] += qv.x * kv.z; sf[0][3] += qv.x * kv.w;
            sf[1][0] += qv.y * kv.x; sf[1][1] += qv.y * kv.y; sf[1][2] += qv.y * kv.z; sf[1][3] += qv.y * kv.w;
            sf[2][0] += qv.z * kv.x; sf[2][1] += qv.z * kv.y; sf[2][2] += qv.z * kv.z; sf[2][3] += qv.z * kv.w;
            sf[3][0] += qv.w * kv.x; sf[3][1] += qv.w * kv.y; sf[3][2] += qv.w * kv.z; sf[3][3] += qv.w * kv.w;
        }

        // causal mask on diagonal tile
        if (t == qb) {
            #pragma unroll
            for (int i = 0; i < 4; i++)
                #pragma unroll
                for (int j = 0; j < 4; j++)
                    if ((tx << 2) + j > (ty << 2) + i) sf[i][j] = -1e30f;
        }

        // online softmax update
        #pragma unroll
        for (int i = 0; i < 4; i++) {
            float mt = fmaxf(fmaxf(sf[i][0], sf[i][1]), fmaxf(sf[i][2], sf[i][3]));
            #pragma unroll
            for (int off = 8; off > 0; off >>= 1)
                mt = fmaxf(mt, __shfl_xor_sync(0xffffffffu, mt, off, 16));
            float mnew = fmaxf(m_i[i], mt);
            float corr = __expf(m_i[i] - mnew);
            m_i[i] = mnew;
            float rs = 0.f;
            #pragma unroll
            for (int j = 0; j < 4; j++) {
                sf[i][j] = __expf(sf[i][j] - mnew);
                rs += sf[i][j];
            }
            #pragma unroll
            for (int off = 8; off > 0; off >>= 1)
                rs += __shfl_xor_sync(0xffffffffu, rs, off, 16);
            l_i[i] = l_i[i] * corr + rs;
            #pragma unroll
            for (int j = 0; j < 4; j++) acc[i][j] *= corr;
        }

        // write P transposed into KPs ([s][row]); everyone done reading K
        __syncthreads();
        #pragma unroll
        for (int i = 0; i < 4; i++)
            #pragma unroll
            for (int j = 0; j < 4; j++)
                KPs[(tx << 2) + j][(ty << 2) + i] = sf[i][j];
        __syncthreads();

        // O += P @ V
        #pragma unroll 16
        for (int ss = 0; ss < 64; ss++) {
            float4 pv = *(const float4*)&KPs[ss][ty << 2];
            float4 vv = *(const float4*)&Vs[ss][tx << 2];
            acc[0][0] += pv.x * vv.x; acc[0][1] += pv.x * vv.y; acc[0][2] += pv.x * vv.z; acc[0][3] += pv.x * vv.w;
            acc[1][0] += pv.y * vv.x; acc[1][1] += pv.y * vv.y; acc[1][2] += pv.y * vv.z; acc[1][3] += pv.y * vv.w;
            acc[2][0] += pv.z * vv.x; acc[2][1] += pv.z * vv.y; acc[2][2] += pv.z * vv.z; acc[2][3] += pv.z * vv.w;
            acc[3][0] += pv.w * vv.x; acc[3][1] += pv.w * vv.y; acc[3][2] += pv.w * vv.z; acc[3][3] += pv.w * vv.w;
        }
    }

    // epilogue: normalize and store
    #pragma unroll
    for (int i = 0; i < 4; i++) {
        float inv = 1.0f / l_i[i];
        float4 o4 = make_float4(acc[i][0] * inv, acc[i][1] * inv,
                                acc[i][2] * inv, acc[i][3] * inv);
        int row = qb * 64 + (ty << 2) + i;
        *(float4*)(o + (size_t)(b * SEQ + row) * DIM + h * HD + (tx << 2)) = o4;
    }
}

// ---------------------------------------------------------------------------
extern "C" void kernel_launch(void* const* d_in, const int* in_sizes, int n_in,
                              void* d_out, int out_size)
{
    const float* x    = (const float*)d_in[0];
    const float* fcos = (const float*)d_in[1];
    const float* fsin = (const float*)d_in[2];
    const float* wq   = (const float*)d_in[3];
    const float* wk   = (const float*)d_in[4];
    const float* wv   = (const float*)d_in[5];
    const float* wo   = (const float*)d_in[6];
    float* out = (float*)d_out;

    void *qp_, *kp_, *vp_, *op_;
    cudaGetSymbolAddress(&qp_, g_q);
    cudaGetSymbolAddress(&kp_, g_k);
    cudaGetSymbolAddress(&vp_, g_v);
    cudaGetSymbolAddress(&op_, g_o);
    float* qp = (float*)qp_;
    float* kp = (float*)kp_;
    float* vp = (float*)vp_;
    float* op = (float*)op_;

    const int M = BATCH * SEQ;   // 4096

    // QKV projections
    gemm_nt_kernel<<<dim3(DIM / 64, M / 64), 256>>>(x, wq, qp, M, DIM, DIM);
    gemm_nt_kernel<<<dim3(KVDIM / 64, M / 64), 256>>>(x, wk, kp, M, KVDIM, DIM);
    gemm_nt_kernel<<<dim3(KVDIM / 64, M / 64), 256>>>(x, wv, vp, M, KVDIM, DIM);

    // RoPE on q and k
    {
        int tq = BATCH * SEQ * NH * HALFD;
        rope_kernel<<<(tq + 255) / 256, 256>>>(qp, fcos, fsin, NH);
        int tk = BATCH * SEQ * NKV * HALFD;
        rope_kernel<<<(tk + 255) / 256, 256>>>(kp, fcos, fsin, NKV);
    }

    // attention
    attn_kernel<<<dim3(SEQ / 64, NH, BATCH), 256>>>(qp, kp, vp, op);

    // output projection
    gemm_nt_kernel<<<dim3(DIM / 64, M / 64), 256>>>(op, wo, out, M, DIM, DIM);
}

// round 4
// speedup vs baseline: 1.8936x; 1.8936x over previous
#include <cuda_runtime.h>
#include <cstdint>

#define BATCH  2
#define SEQ    2048
#define DIM    2048
#define NH     32
#define NKV    8
#define HD     64
#define KVDIM  (NKV*HD)     // 512
#define REP    (NH/NKV)     // 4
#define HALFD  (HD/2)       // 32

// ---------------- scratch (device globals; no allocations allowed) ----------
__device__ __align__(16) float g_q[(size_t)BATCH*SEQ*NH*HD];   // 32 MB
__device__ __align__(16) float g_k[(size_t)BATCH*SEQ*NKV*HD];  // 8 MB
__device__ __align__(16) float g_v[(size_t)BATCH*SEQ*NKV*HD];  // 8 MB
__device__ __align__(16) float g_o[(size_t)BATCH*SEQ*NH*HD];   // 32 MB

// cvt.rna.tf32.f32 needs a .b32 destination register (not .f32)
__device__ __forceinline__ float to_tf32(float x) {
    uint32_t r;
    asm("cvt.rna.tf32.f32 %0, %1;" : "=r"(r) : "f"(x));
    return __uint_as_float(r);
}

// m16n8k8 tf32 mma: D = A(16x8) * B(8x8) + D, A row-major, B K-major
__device__ __forceinline__ void mma_tf32(float c[4], const uint32_t a[4],
                                         const uint32_t b[2]) {
    asm volatile(
        "mma.sync.aligned.m16n8k8.row.col.f32.tf32.tf32.f32 "
        "{%0,%1,%2,%3}, {%4,%5,%6,%7}, {%8,%9}, {%0,%1,%2,%3};"
        : "+f"(c[0]), "+f"(c[1]), "+f"(c[2]), "+f"(c[3])
        : "r"(a[0]), "r"(a[1]), "r"(a[2]), "r"(a[3]),
          "r"(b[0]), "r"(b[1]));
}

// ===========================================================================
// Tensor-core GEMM (tf32 mma.sync): C[M,N] = A[M,K] * W[N,K]^T, row-major.
// 128x128 tile, BK=32, double-buffered smem (stride 36), 256 threads.
// ===========================================================================
#define GBM 128
#define GBN 128
#define GBK 32
#define LDSS 36
#define TILE_FLOATS (GBM * LDSS)             // 4608 floats / buffer
#define GEMM_SMEM_BYTES (4 * TILE_FLOATS * 4)  // 73728

__global__ void __launch_bounds__(256, 1)
gemm_mma_kernel(const float* __restrict__ A, const float* __restrict__ W,
                float* __restrict__ C, int M, int N, int K)
{
    extern __shared__ float sm[];
    float* Asm = sm;                       // [2][128*36]
    float* Wsm = sm + 2 * TILE_FLOATS;     // [2][128*36]

    const int tid  = threadIdx.x;
    const int wid  = tid >> 5;
    const int lane = tid & 31;
    const int g    = lane >> 2;            // groupID 0..7
    const int t    = lane & 3;             // threadID_in_group 0..3
    const int wm0  = (wid >> 2) * 64;      // warp m-offset (0/64)
    const int wn0  = (wid & 3) * 32;       // warp n-offset (0/32/64/96)
    const int m0   = blockIdx.y * GBM;
    const int n0   = blockIdx.x * GBN;

    float c[4][4][4] = {};                 // [mfrag][nfrag][4]

    float4 ra[4], rb[4];

    // ---- prologue: load tile 0 ----
    #pragma unroll
    for (int it = 0; it < 4; it++) {
        int idx = tid + it * 256;
        int row = idx >> 3, c4 = (idx & 7) << 2;
        ra[it] = *(const float4*)(A + (size_t)(m0 + row) * K + c4);
        rb[it] = *(const float4*)(W + (size_t)(n0 + row) * K + c4);
    }
    #pragma unroll
    for (int it = 0; it < 4; it++) {
        int idx = tid + it * 256;
        int row = idx >> 3, c4 = (idx & 7) << 2;
        float* ap = Asm + row * LDSS + c4;
        ap[0] = to_tf32(ra[it].x); ap[1] = to_tf32(ra[it].y);
        ap[2] = to_tf32(ra[it].z); ap[3] = to_tf32(ra[it].w);
        float* wp = Wsm + row * LDSS + c4;
        wp[0] = to_tf32(rb[it].x); wp[1] = to_tf32(rb[it].y);
        wp[2] = to_tf32(rb[it].z); wp[3] = to_tf32(rb[it].w);
    }
    __syncthreads();

    const int nk = K / GBK;
    for (int kt = 0; kt < nk; kt++) {
        const int buf = kt & 1;

        // prefetch next tile into registers
        if (kt + 1 < nk) {
            const int k0 = (kt + 1) * GBK;
            #pragma unroll
            for (int it = 0; it < 4; it++) {
                int idx = tid + it * 256;
                int row = idx >> 3, c4 = (idx & 7) << 2;
                ra[it] = *(const float4*)(A + (size_t)(m0 + row) * K + k0 + c4);
                rb[it] = *(const float4*)(W + (size_t)(n0 + row) * K + k0 + c4);
            }
        }

        // ---- compute on current buffer ----
        const float* Ab = Asm + buf * TILE_FLOATS;
        const float* Wb = Wsm + buf * TILE_FLOATS;
        #pragma unroll
        for (int ks = 0; ks < 4; ks++) {
            const int k0 = ks * 8;
            uint32_t af[4][4], bf[4][2];
            #pragma unroll
            for (int i = 0; i < 4; i++) {
                const float* ap = Ab + (wm0 + i * 16 + g) * LDSS + k0 + t;
                af[i][0] = __float_as_uint(ap[0]);
                af[i][1] = __float_as_uint(ap[8 * LDSS]);
                af[i][2] = __float_as_uint(ap[4]);
                af[i][3] = __float_as_uint(ap[8 * LDSS + 4]);
            }
            #pragma unroll
            for (int j = 0; j < 4; j++) {
                const float* bp = Wb + (wn0 + j * 8 + g) * LDSS + k0 + t;
                bf[j][0] = __float_as_uint(bp[0]);
                bf[j][1] = __float_as_uint(bp[4]);
            }
            #pragma unroll
            for (int i = 0; i < 4; i++)
                #pragma unroll
                for (int j = 0; j < 4; j++)
                    mma_tf32(c[i][j], af[i], bf[j]);
        }

        // store prefetched tile into the other buffer
        if (kt + 1 < nk) {
            float* An = Asm + (buf ^ 1) * TILE_FLOATS;
            float* Wn = Wsm + (buf ^ 1) * TILE_FLOATS;
            #pragma unroll
            for (int it = 0; it < 4; it++) {
                int idx = tid + it * 256;
                int row = idx >> 3, c4 = (idx & 7) << 2;
                float* ap = An + row * LDSS + c4;
                ap[0] = to_tf32(ra[it].x); ap[1] = to_tf32(ra[it].y);
                ap[2] = to_tf32(ra[it].z); ap[3] = to_tf32(ra[it].w);
                float* wp = Wn + row * LDSS + c4;
                wp[0] = to_tf32(rb[it].x); wp[1] = to_tf32(rb[it].y);
                wp[2] = to_tf32(rb[it].z); wp[3] = to_tf32(rb[it].w);
            }
        }
        __syncthreads();
    }

    // ---- epilogue: write accumulators ----
    #pragma unroll
    for (int i = 0; i < 4; i++) {
        #pragma unroll
        for (int j = 0; j < 4; j++) {
            const int row = m0 + wm0 + i * 16 + g;
            const int col = n0 + wn0 + j * 8 + 2 * t;
            *(float2*)(C + (size_t)row * N + col) =
                make_float2(c[i][j][0], c[i][j][1]);
            *(float2*)(C + (size_t)(row + 8) * N + col) =
                make_float2(c[i][j][2], c[i][j][3]);
        }
    }
}

// ---------------------------------------------------------------------------
// RoPE (interleaved pairs), in place. t layout: [B, S, nh, HD].
// ---------------------------------------------------------------------------
__global__ void rope_kernel(float* __restrict__ t,
                            const float* __restrict__ fcos,
                            const float* __restrict__ fsin,
                            int nh)
{
    int idx = blockIdx.x * blockDim.x + threadIdx.x;
    int total = BATCH * SEQ * nh * HALFD;
    if (idx >= total) return;
    int p = idx & (HALFD - 1);
    int h = (idx >> 5) % nh;
    int s = (idx >> 5) / nh % SEQ;
    int b = idx / (HALFD * nh * SEQ);

    float* base = t + (((size_t)(b * SEQ + s) * nh + h) * HD) + 2 * p;
    float cv = fcos[s * HALFD + p];
    float sv = fsin[s * HALFD + p];
    float x0 = base[0], x1 = base[1];
    base[0] = x0 * cv - x1 * sv;
    base[1] = x0 * sv + x1 * cv;
}

// ---------------------------------------------------------------------------
// Flash attention (fp32, causal, GQA). Grid: (S/64, NH, B). 256 threads.
// ---------------------------------------------------------------------------
__global__ void __launch_bounds__(256)
attn_kernel(const float* __restrict__ q, const float* __restrict__ k,
            const float* __restrict__ v, float* __restrict__ o)
{
    __shared__ float Qs[HD][64];
    __shared__ float KPs[64][64];
    __shared__ float Vs[64][64];

    const int qb  = blockIdx.x;
    const int h   = blockIdx.y;
    const int b   = blockIdx.z;
    const int kvh = h / REP;
    const int tid = threadIdx.x;
    const int ty  = tid >> 4;
    const int tx  = tid & 15;

    const float scale = 0.125f;

    for (int i = tid; i < 1024; i += 256) {
        int rr = i >> 4, d4 = (i & 15) << 2;
        float4 v4 = *(const float4*)(q + (size_t)(b * SEQ + qb * 64 + rr) * DIM + h * HD + d4);
        Qs[d4 + 0][rr] = v4.x * scale; Qs[d4 + 1][rr] = v4.y * scale;
        Qs[d4 + 2][rr] = v4.z * scale; Qs[d4 + 3][rr] = v4.w * scale;
    }

    float acc[4][4] = {};
    float m_i[4] = {-1e30f, -1e30f, -1e30f, -1e30f};
    float l_i[4] = {};

    for (int t = 0; t <= qb; t++) {
        const int s0 = t * 64;
        __syncthreads();
        for (int i = tid; i < 1024; i += 256) {
            int cc = i >> 4, d4 = (i & 15) << 2;
            size_t gk = (size_t)(b * SEQ + s0 + cc) * KVDIM + kvh * HD + d4;
            float4 kv4 = *(const float4*)(k + gk);
            KPs[d4 + 0][cc] = kv4.x; KPs[d4 + 1][cc] = kv4.y;
            KPs[d4 + 2][cc] = kv4.z; KPs[d4 + 3][cc] = kv4.w;
            *(float4*)&Vs[cc][d4] = *(const float4*)(v + gk);
        }
        __syncthreads();

        float sf[4][4] = {};
        #pragma unroll 16
        for (int kk = 0; kk < HD; kk++) {
            float4 qv = *(const float4*)&Qs[kk][ty << 2];
            float4 kv = *(const float4*)&KPs[kk][tx << 2];
            sf[0][0] += qv.x * kv.x; sf[0][1] += qv.x * kv.y; sf[0][2] += qv.x * kv.z; sf[0][3] += qv.x * kv.w;
            sf[1][0] += qv.y * kv.x; sf[1][1] += qv.y * kv.y; sf[1][2] += qv.y * kv.z; sf[1][3] += qv.y * kv.w;
            sf[2][0] += qv.z * kv.x; sf[2][1] += qv.z * kv.y; sf[2][2] += qv.z * kv.z; sf[2][3] += qv.z * kv.w;
            sf[3][0] += qv.w * kv.x; sf[3][1] += qv.w * kv.y; sf[3][2] += qv.w * kv.z; sf[3][3] += qv.w * kv.w;
        }

        if (t == qb) {
            #pragma unroll
            for (int i = 0; i < 4; i++)
                #pragma unroll
                for (int j = 0; j < 4; j++)
                    if ((tx << 2) + j > (ty << 2) + i) sf[i][j] = -1e30f;
        }

        #pragma unroll
        for (int i = 0; i < 4; i++) {
            float mt = fmaxf(fmaxf(sf[i][0], sf[i][1]), fmaxf(sf[i][2], sf[i][3]));
            #pragma unroll
            for (int off = 8; off > 0; off >>= 1)
                mt = fmaxf(mt, __shfl_xor_sync(0xffffffffu, mt, off, 16));
            float mnew = fmaxf(m_i[i], mt);
            float corr = __expf(m_i[i] - mnew);
            m_i[i] = mnew;
            float rs = 0.f;
            #pragma unroll
            for (int j = 0; j < 4; j++) {
                sf[i][j] = __expf(sf[i][j] - mnew);
                rs += sf[i][j];
            }
            #pragma unroll
            for (int off = 8; off > 0; off >>= 1)
                rs += __shfl_xor_sync(0xffffffffu, rs, off, 16);
            l_i[i] = l_i[i] * corr + rs;
            #pragma unroll
            for (int j = 0; j < 4; j++) acc[i][j] *= corr;
        }

        __syncthreads();
        #pragma unroll
        for (int i = 0; i < 4; i++)
            #pragma unroll
            for (int j = 0; j < 4; j++)
                KPs[(tx << 2) + j][(ty << 2) + i] = sf[i][j];
        __syncthreads();

        #pragma unroll 16
        for (int ss = 0; ss < 64; ss++) {
            float4 pv = *(const float4*)&KPs[ss][ty << 2];
            float4 vv = *(const float4*)&Vs[ss][tx << 2];
            acc[0][0] += pv.x * vv.x; acc[0][1] += pv.x * vv.y; acc[0][2] += pv.x * vv.z; acc[0][3] += pv.x * vv.w;
            acc[1][0] += pv.y * vv.x; acc[1][1] += pv.y * vv.y; acc[1][2] += pv.y * vv.z; acc[1][3] += pv.y * vv.w;
            acc[2][0] += pv.z * vv.x; acc[2][1] += pv.z * vv.y; acc[2][2] += pv.z * vv.z; acc[2][3] += pv.z * vv.w;
            acc[3][0] += pv.w * vv.x; acc[3][1] += pv.w * vv.y; acc[3][2] += pv.w * vv.z; acc[3][3] += pv.w * vv.w;
        }
    }

    #pragma unroll
    for (int i = 0; i < 4; i++) {
        float inv = 1.0f / l_i[i];
        float4 o4 = make_float4(acc[i][0] * inv, acc[i][1] * inv,
                                acc[i][2] * inv, acc[i][3] * inv);
        int row = qb * 64 + (ty << 2) + i;
        *(float4*)(o + (size_t)(b * SEQ + row) * DIM + h * HD + (tx << 2)) = o4;
    }
}

// ---------------------------------------------------------------------------
extern "C" void kernel_launch(void* const* d_in, const int* in_sizes, int n_in,
                              void* d_out, int out_size)
{
    const float* x    = (const float*)d_in[0];
    const float* fcos = (const float*)d_in[1];
    const float* fsin = (const float*)d_in[2];
    const float* wq   = (const float*)d_in[3];
    const float* wk   = (const float*)d_in[4];
    const float* wv   = (const float*)d_in[5];
    const float* wo   = (const float*)d_in[6];
    float* out = (float*)d_out;

    void *qp_, *kp_, *vp_, *op_;
    cudaGetSymbolAddress(&qp_, g_q);
    cudaGetSymbolAddress(&kp_, g_k);
    cudaGetSymbolAddress(&vp_, g_v);
    cudaGetSymbolAddress(&op_, g_o);
    float* qp = (float*)qp_;
    float* kp = (float*)kp_;
    float* vp = (float*)vp_;
    float* op = (float*)op_;

    const int M = BATCH * SEQ;   // 4096

    cudaFuncSetAttribute(gemm_mma_kernel,
                         cudaFuncAttributeMaxDynamicSharedMemorySize,
                         GEMM_SMEM_BYTES);

    // QKV projections (tf32 mma.sync)
    gemm_mma_kernel<<<dim3(DIM / GBN, M / GBM), 256, GEMM_SMEM_BYTES>>>(x, wq, qp, M, DIM, DIM);
    gemm_mma_kernel<<<dim3(KVDIM / GBN, M / GBM), 256, GEMM_SMEM_BYTES>>>(x, wk, kp, M, KVDIM, DIM);
    gemm_mma_kernel<<<dim3(KVDIM / GBN, M / GBM), 256, GEMM_SMEM_BYTES>>>(x, wv, vp, M, KVDIM, DIM);

    // RoPE on q and k
    {
        int tq = BATCH * SEQ * NH * HALFD;
        rope_kernel<<<(tq + 255) / 256, 256>>>(qp, fcos, fsin, NH);
        int tk = BATCH * SEQ * NKV * HALFD;
        rope_kernel<<<(tk + 255) / 256, 256>>>(kp, fcos, fsin, NKV);
    }

    // attention (fp32 SIMT this round)
    attn_kernel<<<dim3(SEQ / 64, NH, BATCH), 256>>>(qp, kp, vp, op);

    // output projection (tf32 mma.sync)
    gemm_mma_kernel<<<dim3(DIM / GBN, M / GBM), 256, GEMM_SMEM_BYTES>>>(op, wo, out, M, DIM, DIM);
}

// round 5
// speedup vs baseline: 3.5862x; 1.8938x over previous
#include <cuda_runtime.h>
#include <cstdint>

#define BATCH  2
#define SEQ    2048
#define DIM    2048
#define NH     32
#define NKV    8
#define HD     64
#define KVDIM  (NKV*HD)     // 512
#define REP    (NH/NKV)     // 4
#define HALFD  (HD/2)       // 32

// ---------------- scratch (device globals; no allocations allowed) ----------
__device__ __align__(16) float g_q[(size_t)BATCH*SEQ*NH*HD];   // 32 MB
__device__ __align__(16) float g_k[(size_t)BATCH*SEQ*NKV*HD];  // 8 MB
__device__ __align__(16) float g_v[(size_t)BATCH*SEQ*NKV*HD];  // 8 MB
__device__ __align__(16) float g_o[(size_t)BATCH*SEQ*NH*HD];   // 32 MB

// cvt.rna.tf32.f32 needs a .b32 destination register
__device__ __forceinline__ uint32_t tf32u(float x) {
    uint32_t r;
    asm("cvt.rna.tf32.f32 %0, %1;" : "=r"(r) : "f"(x));
    return r;
}
__device__ __forceinline__ float tf32f(float x) {
    return __uint_as_float(tf32u(x));
}
__device__ __forceinline__ float to_tf32(float x) { return tf32f(x); }

// m16n8k8 tf32 mma: D = A(16x8) * B(8x8) + D, A row-major, B K-major
__device__ __forceinline__ void mma_tf32(float c[4], const uint32_t a[4],
                                         const uint32_t b[2]) {
    asm volatile(
        "mma.sync.aligned.m16n8k8.row.col.f32.tf32.tf32.f32 "
        "{%0,%1,%2,%3}, {%4,%5,%6,%7}, {%8,%9}, {%0,%1,%2,%3};"
        : "+f"(c[0]), "+f"(c[1]), "+f"(c[2]), "+f"(c[3])
        : "r"(a[0]), "r"(a[1]), "r"(a[2]), "r"(a[3]),
          "r"(b[0]), "r"(b[1]));
}

// ===========================================================================
// Tensor-core GEMM (tf32 mma.sync): C[M,N] = A[M,K] * W[N,K]^T, row-major.
// 128x128 tile, BK=32, double-buffered smem (stride 36), 256 threads.
// ===========================================================================
#define GBM 128
#define GBN 128
#define GBK 32
#define LDSS 36
#define TILE_FLOATS (GBM * LDSS)               // 4608 floats / buffer
#define GEMM_SMEM_BYTES (4 * TILE_FLOATS * 4)  // 73728

__global__ void __launch_bounds__(256, 1)
gemm_mma_kernel(const float* __restrict__ A, const float* __restrict__ W,
                float* __restrict__ C, int M, int N, int K)
{
    extern __shared__ float sm[];
    float* Asm = sm;                       // [2][128*36]
    float* Wsm = sm + 2 * TILE_FLOATS;     // [2][128*36]

    const int tid  = threadIdx.x;
    const int wid  = tid >> 5;
    const int lane = tid & 31;
    const int g    = lane >> 2;
    const int t    = lane & 3;
    const int wm0  = (wid >> 2) * 64;
    const int wn0  = (wid & 3) * 32;
    const int m0   = blockIdx.y * GBM;
    const int n0   = blockIdx.x * GBN;

    float c[4][4][4] = {};
    float4 ra[4], rb[4];

    #pragma unroll
    for (int it = 0; it < 4; it++) {
        int idx = tid + it * 256;
        int row = idx >> 3, c4 = (idx & 7) << 2;
        ra[it] = *(const float4*)(A + (size_t)(m0 + row) * K + c4);
        rb[it] = *(const float4*)(W + (size_t)(n0 + row) * K + c4);
    }
    #pragma unroll
    for (int it = 0; it < 4; it++) {
        int idx = tid + it * 256;
        int row = idx >> 3, c4 = (idx & 7) << 2;
        float* ap = Asm + row * LDSS + c4;
        ap[0] = to_tf32(ra[it].x); ap[1] = to_tf32(ra[it].y);
        ap[2] = to_tf32(ra[it].z); ap[3] = to_tf32(ra[it].w);
        float* wp = Wsm + row * LDSS + c4;
        wp[0] = to_tf32(rb[it].x); wp[1] = to_tf32(rb[it].y);
        wp[2] = to_tf32(rb[it].z); wp[3] = to_tf32(rb[it].w);
    }
    __syncthreads();

    const int nk = K / GBK;
    for (int kt = 0; kt < nk; kt++) {
        const int buf = kt & 1;

        if (kt + 1 < nk) {
            const int k0 = (kt + 1) * GBK;
            #pragma unroll
            for (int it = 0; it < 4; it++) {
                int idx = tid + it * 256;
                int row = idx >> 3, c4 = (idx & 7) << 2;
                ra[it] = *(const float4*)(A + (size_t)(m0 + row) * K + k0 + c4);
                rb[it] = *(const float4*)(W + (size_t)(n0 + row) * K + k0 + c4);
            }
        }

        const float* Ab = Asm + buf * TILE_FLOATS;
        const float* Wb = Wsm + buf * TILE_FLOATS;
        #pragma unroll
        for (int ks = 0; ks < 4; ks++) {
            const int k0 = ks * 8;
            uint32_t af[4][4], bf[4][2];
            #pragma unroll
            for (int i = 0; i < 4; i++) {
                const float* ap = Ab + (wm0 + i * 16 + g) * LDSS + k0 + t;
                af[i][0] = __float_as_uint(ap[0]);
                af[i][1] = __float_as_uint(ap[8 * LDSS]);
                af[i][2] = __float_as_uint(ap[4]);
                af[i][3] = __float_as_uint(ap[8 * LDSS + 4]);
            }
            #pragma unroll
            for (int j = 0; j < 4; j++) {
                const float* bp = Wb + (wn0 + j * 8 + g) * LDSS + k0 + t;
                bf[j][0] = __float_as_uint(bp[0]);
                bf[j][1] = __float_as_uint(bp[4]);
            }
            #pragma unroll
            for (int i = 0; i < 4; i++)
                #pragma unroll
                for (int j = 0; j < 4; j++)
                    mma_tf32(c[i][j], af[i], bf[j]);
        }

        if (kt + 1 < nk) {
            float* An = Asm + (buf ^ 1) * TILE_FLOATS;
            float* Wn = Wsm + (buf ^ 1) * TILE_FLOATS;
            #pragma unroll
            for (int it = 0; it < 4; it++) {
                int idx = tid + it * 256;
                int row = idx >> 3, c4 = (idx & 7) << 2;
                float* ap = An + row * LDSS + c4;
                ap[0] = to_tf32(ra[it].x); ap[1] = to_tf32(ra[it].y);
                ap[2] = to_tf32(ra[it].z); ap[3] = to_tf32(ra[it].w);
                float* wp = Wn + row * LDSS + c4;
                wp[0] = to_tf32(rb[it].x); wp[1] = to_tf32(rb[it].y);
                wp[2] = to_tf32(rb[it].z); wp[3] = to_tf32(rb[it].w);
            }
        }
        __syncthreads();
    }

    #pragma unroll
    for (int i = 0; i < 4; i++) {
        #pragma unroll
        for (int j = 0; j < 4; j++) {
            const int row = m0 + wm0 + i * 16 + g;
            const int col = n0 + wn0 + j * 8 + 2 * t;
            *(float2*)(C + (size_t)row * N + col) =
                make_float2(c[i][j][0], c[i][j][1]);
            *(float2*)(C + (size_t)(row + 8) * N + col) =
                make_float2(c[i][j][2], c[i][j][3]);
        }
    }
}

// ---------------------------------------------------------------------------
// RoPE (interleaved pairs), in place. t layout: [B, S, nh, HD].
// ---------------------------------------------------------------------------
__global__ void rope_kernel(float* __restrict__ t,
                            const float* __restrict__ fcos,
                            const float* __restrict__ fsin,
                            int nh)
{
    int idx = blockIdx.x * blockDim.x + threadIdx.x;
    int total = BATCH * SEQ * nh * HALFD;
    if (idx >= total) return;
    int p = idx & (HALFD - 1);
    int h = (idx >> 5) % nh;
    int s = (idx >> 5) / nh % SEQ;
    int b = idx / (HALFD * nh * SEQ);

    float* base = t + (((size_t)(b * SEQ + s) * nh + h) * HD) + 2 * p;
    float cv = fcos[s * HALFD + p];
    float sv = fsin[s * HALFD + p];
    float x0 = base[0], x1 = base[1];
    base[0] = x0 * cv - x1 * sv;
    base[1] = x0 * sv + x1 * cv;
}

// ===========================================================================
// Flash attention with tf32 mma.sync. Causal, GQA.
// Block: 128 q-rows x 64 kv tile, 8 warps (16 q-rows each, full kv width).
// Grid: (S/128, NH, B). Smem: K[64][68] + Vt[64][68] + P[128][68] = 68KB.
// ===========================================================================
#define LDK 68
#define ATT_SMEM_BYTES ((64 * LDK + 64 * LDK + 128 * LDK) * 4)  // 69632

__global__ void __launch_bounds__(256, 1)
attn_mma_kernel(const float* __restrict__ q, const float* __restrict__ k,
                const float* __restrict__ v, float* __restrict__ o)
{
    extern __shared__ float sma[];
    float* Ks = sma;                 // [kv=64][hd], stride LDK
    float* Vt = sma + 64 * LDK;      // [hd=64][kv], stride LDK (V transposed)
    float* Ps = sma + 128 * LDK;     // [qrow=128][kv], stride LDK

    const int qb   = blockIdx.x;
    const int h    = blockIdx.y;
    const int b    = blockIdx.z;
    const int kvh  = h / REP;
    const int tid  = threadIdx.x;
    const int wid  = tid >> 5;
    const int lane = tid & 31;
    const int g    = lane >> 2;
    const int t    = lane & 3;
    const int R0   = qb * 128 + wid * 16;     // warp's first global q-row
    float* Pw = Ps + (wid * 16) * LDK;

    // ---- Q fragments (registers, scaled, tf32) ----
    uint32_t aq[8][4];
    {
        const float* q0 = q + ((size_t)b * SEQ + R0 + g) * DIM + h * HD;
        #pragma unroll
        for (int kf = 0; kf < 8; kf++) {
            aq[kf][0] = tf32u(q0[kf * 8 + t] * 0.125f);
            aq[kf][1] = tf32u(q0[8 * DIM + kf * 8 + t] * 0.125f);
            aq[kf][2] = tf32u(q0[kf * 8 + t + 4] * 0.125f);
            aq[kf][3] = tf32u(q0[8 * DIM + kf * 8 + t + 4] * 0.125f);
        }
    }

    float co[8][4] = {};
    float mr0 = -1e30f, mr1 = -1e30f;
    float lr0 = 0.f, lr1 = 0.f;

    const int ntiles = 2 * qb + 2;
    for (int ti = 0; ti < ntiles; ti++) {
        __syncthreads();
        // ---- load K and V (transposed) tiles ----
        {
            const int r  = tid >> 2;             // 0..63 kv row
            const int c0 = (tid & 3) << 4;       // 0,16,32,48
            const size_t gbase = ((size_t)b * SEQ + ti * 64 + r) * KVDIM + kvh * HD + c0;
            const float* kp = k + gbase;
            const float* vp = v + gbase;
            #pragma unroll
            for (int i = 0; i < 4; i++) {
                float4 k4 = *(const float4*)(kp + i * 4);
                float* kd = Ks + r * LDK + c0 + i * 4;
                kd[0] = tf32f(k4.x); kd[1] = tf32f(k4.y);
                kd[2] = tf32f(k4.z); kd[3] = tf32f(k4.w);
                float4 v4 = *(const float4*)(vp + i * 4);
                Vt[(c0 + i * 4 + 0) * LDK + r] = tf32f(v4.x);
                Vt[(c0 + i * 4 + 1) * LDK + r] = tf32f(v4.y);
                Vt[(c0 + i * 4 + 2) * LDK + r] = tf32f(v4.z);
                Vt[(c0 + i * 4 + 3) * LDK + r] = tf32f(v4.w);
            }
        }
        __syncthreads();

        if (ti * 64 > R0 + 15) continue;   // warp entirely above diagonal

        // ---- S = Q K^T (m16 x n64, k=64) ----
        float cs[8][4] = {};
        #pragma unroll
        for (int kf = 0; kf < 8; kf++) {
            #pragma unroll
            for (int nf = 0; nf < 8; nf++) {
                uint32_t bb[2];
                bb[0] = __float_as_uint(Ks[(nf * 8 + g) * LDK + kf * 8 + t]);
                bb[1] = __float_as_uint(Ks[(nf * 8 + g) * LDK + kf * 8 + t + 4]);
                mma_tf32(cs[nf], aq[kf], bb);
            }
        }

        // ---- causal mask (partial tiles only) ----
        const int colbase = ti * 64;
        if (colbase + 63 > R0) {
            const int row0 = R0 + g, row1 = R0 + g + 8;
            #pragma unroll
            for (int nf = 0; nf < 8; nf++) {
                const int c0i = colbase + nf * 8 + 2 * t;
                if (c0i     > row0) cs[nf][0] = -1e9f;
                if (c0i + 1 > row0) cs[nf][1] = -1e9f;
                if (c0i     > row1) cs[nf][2] = -1e9f;
                if (c0i + 1 > row1) cs[nf][3] = -1e9f;
            }
        }

        // ---- online softmax (rows R0+g and R0+g+8, reduce over quad) ----
        float mx0 = -1e30f, mx1 = -1e30f;
        #pragma unroll
        for (int nf = 0; nf < 8; nf++) {
            mx0 = fmaxf(mx0, fmaxf(cs[nf][0], cs[nf][1]));
            mx1 = fmaxf(mx1, fmaxf(cs[nf][2], cs[nf][3]));
        }
        mx0 = fmaxf(mx0, __shfl_xor_sync(0xffffffffu, mx0, 1));
        mx0 = fmaxf(mx0, __shfl_xor_sync(0xffffffffu, mx0, 2));
        mx1 = fmaxf(mx1, __shfl_xor_sync(0xffffffffu, mx1, 1));
        mx1 = fmaxf(mx1, __shfl_xor_sync(0xffffffffu, mx1, 2));

        const float mn0 = fmaxf(mr0, mx0);
        const float mn1 = fmaxf(mr1, mx1);
        const float corr0 = __expf(mr0 - mn0);
        const float corr1 = __expf(mr1 - mn1);
        mr0 = mn0; mr1 = mn1;

        float rs0 = 0.f, rs1 = 0.f;
        #pragma unroll
        for (int nf = 0; nf < 8; nf++) {
            cs[nf][0] = __expf(cs[nf][0] - mn0);
            cs[nf][1] = __expf(cs[nf][1] - mn0);
            cs[nf][2] = __expf(cs[nf][2] - mn1);
            cs[nf][3] = __expf(cs[nf][3] - mn1);
            rs0 += cs[nf][0] + cs[nf][1];
            rs1 += cs[nf][2] + cs[nf][3];
        }
        rs0 += __shfl_xor_sync(0xffffffffu, rs0, 1);
        rs0 += __shfl_xor_sync(0xffffffffu, rs0, 2);
        rs1 += __shfl_xor_sync(0xffffffffu, rs1, 1);
        rs1 += __shfl_xor_sync(0xffffffffu, rs1, 2);
        lr0 = lr0 * corr0 + rs0;
        lr1 = lr1 * corr1 + rs1;
        #pragma unroll
        for (int nf = 0; nf < 8; nf++) {
            co[nf][0] *= corr0; co[nf][1] *= corr0;
            co[nf][2] *= corr1; co[nf][3] *= corr1;
        }

        // ---- P -> smem (warp-private rows), then PV mma ----
        #pragma unroll
        for (int nf = 0; nf < 8; nf++) {
            *(float2*)(Pw + g * LDK + nf * 8 + 2 * t) =
                make_float2(tf32f(cs[nf][0]), tf32f(cs[nf][1]));
            *(float2*)(Pw + (g + 8) * LDK + nf * 8 + 2 * t) =
                make_float2(tf32f(cs[nf][2]), tf32f(cs[nf][3]));
        }
        __syncwarp();

        #pragma unroll
        for (int kf = 0; kf < 8; kf++) {
            uint32_t ap[4];
            ap[0] = __float_as_uint(Pw[g * LDK + kf * 8 + t]);
            ap[1] = __float_as_uint(Pw[(g + 8) * LDK + kf * 8 + t]);
            ap[2] = __float_as_uint(Pw[g * LDK + kf * 8 + t + 4]);
            ap[3] = __float_as_uint(Pw[(g + 8) * LDK + kf * 8 + t + 4]);
            #pragma unroll
            for (int nf = 0; nf < 8; nf++) {
                uint32_t bv[2];
                bv[0] = __float_as_uint(Vt[(nf * 8 + g) * LDK + kf * 8 + t]);
                bv[1] = __float_as_uint(Vt[(nf * 8 + g) * LDK + kf * 8 + t + 4]);
                mma_tf32(co[nf], ap, bv);
            }
        }
    }

    // ---- epilogue ----
    const float inv0 = 1.f / lr0;
    const float inv1 = 1.f / lr1;
    float* o0 = o + ((size_t)b * SEQ + R0 + g) * DIM + h * HD;
    #pragma unroll
    for (int nf = 0; nf < 8; nf++) {
        *(float2*)(o0 + nf * 8 + 2 * t) =
            make_float2(co[nf][0] * inv0, co[nf][1] * inv0);
        *(float2*)(o0 + 8 * DIM + nf * 8 + 2 * t) =
            make_float2(co[nf][2] * inv1, co[nf][3] * inv1);
    }
}

// ---------------------------------------------------------------------------
extern "C" void kernel_launch(void* const* d_in, const int* in_sizes, int n_in,
                              void* d_out, int out_size)
{
    const float* x    = (const float*)d_in[0];
    const float* fcos = (const float*)d_in[1];
    const float* fsin = (const float*)d_in[2];
    const float* wq   = (const float*)d_in[3];
    const float* wk   = (const float*)d_in[4];
    const float* wv   = (const float*)d_in[5];
    const float* wo   = (const float*)d_in[6];
    float* out = (float*)d_out;

    void *qp_, *kp_, *vp_, *op_;
    cudaGetSymbolAddress(&qp_, g_q);
    cudaGetSymbolAddress(&kp_, g_k);
    cudaGetSymbolAddress(&vp_, g_v);
    cudaGetSymbolAddress(&op_, g_o);
    float* qp = (float*)qp_;
    float* kp = (float*)kp_;
    float* vp = (float*)vp_;
    float* op = (float*)op_;

    const int M = BATCH * SEQ;   // 4096

    cudaFuncSetAttribute(gemm_mma_kernel,
                         cudaFuncAttributeMaxDynamicSharedMemorySize,
                         GEMM_SMEM_BYTES);
    cudaFuncSetAttribute(attn_mma_kernel,
                         cudaFuncAttributeMaxDynamicSharedMemorySize,
                         ATT_SMEM_BYTES);

    // QKV projections (tf32 mma.sync)
    gemm_mma_kernel<<<dim3(DIM / GBN, M / GBM), 256, GEMM_SMEM_BYTES>>>(x, wq, qp, M, DIM, DIM);
    gemm_mma_kernel<<<dim3(KVDIM / GBN, M / GBM), 256, GEMM_SMEM_BYTES>>>(x, wk, kp, M, KVDIM, DIM);
    gemm_mma_kernel<<<dim3(KVDIM / GBN, M / GBM), 256, GEMM_SMEM_BYTES>>>(x, wv, vp, M, KVDIM, DIM);

    // RoPE on q and k
    {
        int tq = BATCH * SEQ * NH * HALFD;
        rope_kernel<<<(tq + 255) / 256, 256>>>(qp, fcos, fsin, NH);
        int tk = BATCH * SEQ * NKV * HALFD;
        rope_kernel<<<(tk + 255) / 256, 256>>>(kp, fcos, fsin, NKV);
    }

    // attention (tf32 mma.sync flash attention)
    attn_mma_kernel<<<dim3(SEQ / 128, NH, BATCH), 256, ATT_SMEM_BYTES>>>(qp, kp, vp, op);

    // output projection (tf32 mma.sync)
    gemm_mma_kernel<<<dim3(DIM / GBN, M / GBM), 256, GEMM_SMEM_BYTES>>>(op, wo, out, M, DIM, DIM);
}